// round 14
// baseline (speedup 1.0000x reference)
#include <cuda_runtime.h>

#define TPB   256
#define NBLK  912       // 152 SMs * 6 resident blocks
#define LMIN  2048      // rows shorter than this go to the corner path

// ---------------------------------------------------------------------------
// out = sum_i x[i]*c[i] + sum_{i<j} x[i]*x[j]*c2[base(i)+(j-i-1)]
// c2 = c + n, base(i) = i*(2n-1-i)/2  (row-major packed upper triangle).
//
// Main region (rows 0..n-LMIN-1): each block streams a CONTIGUOUS
// element-balanced slice of the flat triangle, row by row. Per row: uniform
// xi and j-offset, aligned float4 coeff loads (__ldcs), x window as two
// float4 L1 reads + static shift select (template on s). 2-row-unrolled:
// 6 LDG.128 in flight, induction-only addresses.
// Corner region (last LMIN rows, 6.2%): per-element sqrt decode.
// Single kernel: block partials + wrap-around counter; last block reduces.
// ---------------------------------------------------------------------------

__device__ float        g_parts[NBLK];
__device__ unsigned int g_ctr = 0;

__device__ __forceinline__ float warp_sum(float v) {
    #pragma unroll
    for (int o = 16; o > 0; o >>= 1) v += __shfl_down_sync(0xffffffffu, v, o);
    return v;
}

// 4-float window starting S into the 8-float concat (a, b); S static.
template <int S>
__device__ __forceinline__ float4 shift_win(float4 a, float4 b) {
    if (S == 0) return a;
    if (S == 1) return make_float4(a.y, a.z, a.w, b.x);
    if (S == 2) return make_float4(a.z, a.w, b.x, b.y);
    return make_float4(a.w, b.x, b.y, b.z);
}

template <int S>
__device__ __forceinline__ void row_body(float4& acc4,
                                         const float4* __restrict__ cv,
                                         const float4* __restrict__ xv,
                                         int nvec, int t) {
    int v = t;
    for (; v + TPB < nvec; v += 2 * TPB) {       // 6 LDG.128 in flight
        float4 c0 = __ldcs(cv + v);
        float4 c1 = __ldcs(cv + v + TPB);
        float4 a0 = __ldg(xv + v);
        float4 a1 = __ldg(xv + v + TPB);
        float4 w0, w1;
        if (S == 0) {
            w0 = a0; w1 = a1;
        } else {
            float4 b0 = __ldg(xv + v + 1);
            float4 b1 = __ldg(xv + v + TPB + 1);
            w0 = shift_win<S>(a0, b0);
            w1 = shift_win<S>(a1, b1);
        }
        acc4.x = fmaf(c0.x, w0.x, acc4.x);
        acc4.y = fmaf(c0.y, w0.y, acc4.y);
        acc4.z = fmaf(c0.z, w0.z, acc4.z);
        acc4.w = fmaf(c0.w, w0.w, acc4.w);
        acc4.x = fmaf(c1.x, w1.x, acc4.x);
        acc4.y = fmaf(c1.y, w1.y, acc4.y);
        acc4.z = fmaf(c1.z, w1.z, acc4.z);
        acc4.w = fmaf(c1.w, w1.w, acc4.w);
    }
    if (v < nvec) {
        float4 c0 = __ldcs(cv + v);
        float4 a0 = __ldg(xv + v);
        float4 w0;
        if (S == 0) {
            w0 = a0;
        } else {
            float4 b0 = __ldg(xv + v + 1);
            w0 = shift_win<S>(a0, b0);
        }
        acc4.x = fmaf(c0.x, w0.x, acc4.x);
        acc4.y = fmaf(c0.y, w0.y, acc4.y);
        acc4.z = fmaf(c0.z, w0.z, acc4.z);
        acc4.w = fmaf(c0.w, w0.w, acc4.w);
    }
}

__global__ __launch_bounds__(TPB)
void ham_kernel(const float* __restrict__ x,
                const float* __restrict__ c,
                float* __restrict__ out,
                int n) {
    const int t = threadIdx.x;
    const int b = blockIdx.x;
    const int G = gridDim.x;
    const float* c2 = c + n;

    const int total = (n * (n - 1)) >> 1;                 // 33,550,336
    const int ilong = n - LMIN;                           // 6144
    const int gc    = (ilong * (2 * n - 1 - ilong)) >> 1; // 31,454,208

    float sum = 0.0f;

    // degree-1 terms, spread over all blocks
    for (int k = b * TPB + t; k < n; k += G * TPB)
        sum += __ldg(x + k) * __ldg(c + k);

    // ---- main region: contiguous element-balanced slice of [0, gc) ----
    const int e0 = (int)(((long long)b       * gc) / G);
    const int e1 = (int)(((long long)(b + 1) * gc) / G);

    if (e0 < e1) {
        // decode starting row (double seed + exact fixup)
        const double nd = 2.0 * (double)n - 1.0;
        int i = (int)((nd - sqrt(nd * nd - 8.0 * (double)e0)) * 0.5);
        if (i < 0) i = 0;
        if (i > n - 2) i = n - 2;
        int rb = (i * (2 * n - 1 - i)) >> 1;
        while (rb > e0) { --i; rb -= (n - 1 - i); }
        while (e0 >= rb + (n - 1 - i)) { rb += (n - 1 - i); ++i; }
        int re = rb + (n - 1 - i);

        int g = e0;
        while (g < e1) {
            const int send = re < e1 ? re : e1;   // row slice [g, send)
            const float xi  = __ldg(x + i);
            const int  joff = i + 1 - rb;         // j = g + joff

            // scalar head until coeff pointer is 16B aligned
            int h = (4 - (g & 3)) & 3;
            if (h > send - g) h = send - g;
            if (t < h)
                sum += xi * __ldcs(c2 + g + t) * __ldg(x + g + t + joff);

            const int gv  = g + h;
            const int rem = send - gv;
            int nvec = rem >> 2;
            int tail = rem & 3;
            const int jb = gv + joff;             // first j of vector body
            const int s  = jb & 3;
            if (s != 0 && nvec > 0) { nvec -= 1; tail += 4; }

            const float4* cv = reinterpret_cast<const float4*>(c2 + gv);
            const float4* xv = reinterpret_cast<const float4*>(x + (jb - s));

            float4 a4 = make_float4(0.f, 0.f, 0.f, 0.f);
            switch (s) {
                case 0: row_body<0>(a4, cv, xv, nvec, t); break;
                case 1: row_body<1>(a4, cv, xv, nvec, t); break;
                case 2: row_body<2>(a4, cv, xv, nvec, t); break;
                default: row_body<3>(a4, cv, xv, nvec, t); break;
            }
            sum += xi * ((a4.x + a4.y) + (a4.z + a4.w));

            // scalar tail (up to 7 elements)
            const int gd = gv + 4 * nvec;
            if (t < tail)
                sum += xi * __ldcs(c2 + gd + t) * __ldg(x + gd + t + joff);

            g = send;
            if (g == re) { rb = re; ++i; re += (n - 1 - i); }
        }
    }

    // ---- corner region [gc, total): per-element sqrt decode ----
    {
        const double nd = 2.0 * (double)n - 1.0;
        for (int g = gc + b * TPB + t; g < total; g += G * TPB) {
            int i = (int)((nd - sqrt(nd * nd - 8.0 * (double)g)) * 0.5);
            if (i < 0) i = 0;
            if (i > n - 2) i = n - 2;
            int rb = (i * (2 * n - 1 - i)) >> 1;
            while (rb > g) { --i; rb -= (n - 1 - i); }
            while (g >= rb + (n - 1 - i)) { rb += (n - 1 - i); ++i; }
            const int j = g - rb + i + 1;
            sum = fmaf(__ldcs(c2 + g), __ldg(x + i) * __ldg(x + j), sum);
        }
    }

    // ---- block partial -> counter -> last block reduces + writes out ----
    __shared__ float wsum[TPB / 32];
    __shared__ int lastflag;
    float w = warp_sum(sum);
    if ((t & 31) == 0) wsum[t >> 5] = w;
    __syncthreads();
    if (t < 32) {
        float v = (t < TPB / 32) ? wsum[t] : 0.0f;
        v = warp_sum(v);
        if (t == 0) {
            g_parts[b] = v;
            __threadfence();
            unsigned int old = atomicInc(&g_ctr, (unsigned)(G - 1));
            lastflag = (old == (unsigned)(G - 1));
        }
    }
    __syncthreads();
    if (lastflag) {
        __threadfence();
        float v = 0.0f;
        for (int k = t; k < G; k += TPB) v += g_parts[k];
        float w2 = warp_sum(v);
        if ((t & 31) == 0) wsum[t >> 5] = w2;
        __syncthreads();
        if (t == 0) {
            float s2 = 0.0f;
            #pragma unroll
            for (int k = 0; k < TPB / 32; ++k) s2 += wsum[k];
            out[0] = s2;
        }
    }
}

extern "C" void kernel_launch(void* const* d_in, const int* in_sizes, int n_in,
                              void* d_out, int out_size) {
    const float* x = (const float*)d_in[0];
    const float* c = (const float*)d_in[1];
    float* out = (float*)d_out;
    const int n = in_sizes[0];   // 8192

    ham_kernel<<<NBLK, TPB>>>(x, c, out, n);
}

// round 15
// speedup vs baseline: 2.6734x; 2.6734x over previous
#include <cuda_runtime.h>

#define TPB     256
#define NBLOCKS 912      // persistent: ~6 blocks/SM
#define W       512      // column-strip width (= 2 * TPB)
#define H       16       // rows per tile

// ---------------------------------------------------------------------------
// out = sum_j x[j] * ( c1[j] + sum_{i<j} x[i] * c2[base(i) + (j-i-1)] )
// c2 = c + n, base(i) = i*(2n-1-i)/2  (row-major packed upper triangle).
//
// EXACT R3 hot path (best measured: 28.3us kernel, DRAM 61.8%):
// Tile (it, js): rows i in [it*H, it*H+H), columns j in [js*W, js*W+W).
// Thread t owns columns j_a = js*W + t and j_b = js*W + TPB + t with one
// register accumulator per column; inner i-loop reads ONLY the coeff stream
// (coalesced LDG.32, evict-first) plus one uniform x[i] per row.
// NEW vs R3: single kernel — block partials + wrap-around arrival counter;
// the last block reduces partials and writes out[0] (no zero kernel).
// ---------------------------------------------------------------------------

__device__ float        g_parts[NBLOCKS];
__device__ unsigned int g_ctr = 0;

__device__ __forceinline__ float warp_sum(float v) {
    #pragma unroll
    for (int o = 16; o > 0; o >>= 1) v += __shfl_down_sync(0xffffffffu, v, o);
    return v;
}

__global__ __launch_bounds__(TPB, 6)
void ham_kernel(const float* __restrict__ x,
                const float* __restrict__ c,
                float* __restrict__ out,
                int n) {
    const int t = threadIdx.x;
    const int b = blockIdx.x;
    const int G = gridDim.x;
    const float* c2 = c + n;

    const int nstrips = n / W;                                   // 16
    const int ntiles  = (W / H / 2) * nstrips * (nstrips + 1);   // 4352

    float sum = 0.0f;

    for (int f = b; f < ntiles; f += G) {
        // strip js: tiles-per-strip = 32*(js+1), prefix(js) = 16*js*(js+1)
        int js = 0;
        while (js + 1 < nstrips && 16 * (js + 1) * (js + 2) <= f) js++;
        const int it = f - 16 * js * (js + 1);

        const int j0  = js * W;
        const int i0  = it * H;
        const int j_a = j0 + t;
        const int j_b = j0 + TPB + t;

        float acc0 = 0.0f, acc1 = 0.0f;
        if (it == 0) {                       // fold degree-1 terms in once
            acc0 = __ldg(c + j_a);
            acc1 = __ldg(c + j_b);
        }

        // rows valid while i < max j in strip:  i < (js+1)*W - 1
        int iend = i0 + H;
        const int ilim = (js + 1) * W - 1;
        if (iend > ilim) iend = ilim;

        const int base = (i0 * (2 * n - 1 - i0)) >> 1;   // < 2^27, exact
        const float* p = c2 + base + (j_a - i0 - 1);

        if (i0 + H <= j0) {
            // ---- clean path: whole tile strictly above diagonal ----
            #pragma unroll 1
            for (int i = i0; i + 4 <= iend; i += 4) {
                const int o1 = n - 2 - i;
                const int o2 = 2 * n - 5 - 2 * i;
                const int o3 = 3 * n - 9 - 3 * i;
                const float xi0 = __ldg(x + i);
                const float xi1 = __ldg(x + i + 1);
                const float xi2 = __ldg(x + i + 2);
                const float xi3 = __ldg(x + i + 3);
                // 8 independent streaming loads in flight
                const float a0 = __ldcs(p);
                const float b0 = __ldcs(p + TPB);
                const float a1 = __ldcs(p + o1);
                const float b1 = __ldcs(p + o1 + TPB);
                const float a2 = __ldcs(p + o2);
                const float b2 = __ldcs(p + o2 + TPB);
                const float a3 = __ldcs(p + o3);
                const float b3 = __ldcs(p + o3 + TPB);
                acc0 = fmaf(xi0, a0, acc0);  acc1 = fmaf(xi0, b0, acc1);
                acc0 = fmaf(xi1, a1, acc0);  acc1 = fmaf(xi1, b1, acc1);
                acc0 = fmaf(xi2, a2, acc0);  acc1 = fmaf(xi2, b2, acc1);
                acc0 = fmaf(xi3, a3, acc0);  acc1 = fmaf(xi3, b3, acc1);
                p += 4 * n - 14 - 4 * i;
            }
        } else {
            // ---- diagonal path: predicate j > i per element ----
            for (int i = i0; i < iend; ++i) {
                const float xi = __ldg(x + i);
                float ca = 0.0f, cb = 0.0f;
                if (j_a > i) ca = __ldcs(p);
                if (j_b > i) cb = __ldcs(p + TPB);
                acc0 = fmaf(xi, ca, acc0);
                acc1 = fmaf(xi, cb, acc1);
                p += n - 2 - i;
            }
        }

        sum += acc0 * __ldg(x + j_a) + acc1 * __ldg(x + j_b);
    }

    // ---- block partial -> counter -> last block reduces + writes out ----
    __shared__ float wsum[TPB / 32];
    __shared__ int lastflag;
    float w = warp_sum(sum);
    if ((t & 31) == 0) wsum[t >> 5] = w;
    __syncthreads();
    if (t < 32) {
        float v = (t < TPB / 32) ? wsum[t] : 0.0f;
        v = warp_sum(v);
        if (t == 0) {
            g_parts[b] = v;
            __threadfence();
            unsigned int old = atomicInc(&g_ctr, (unsigned)(G - 1));
            lastflag = (old == (unsigned)(G - 1));
        }
    }
    __syncthreads();
    if (lastflag) {
        __threadfence();
        float v = 0.0f;
        for (int k = t; k < G; k += TPB) v += g_parts[k];
        float w2 = warp_sum(v);
        if ((t & 31) == 0) wsum[t >> 5] = w2;
        __syncthreads();
        if (t == 0) {
            float s2 = 0.0f;
            #pragma unroll
            for (int k = 0; k < TPB / 32; ++k) s2 += wsum[k];
            out[0] = s2;
        }
    }
}

extern "C" void kernel_launch(void* const* d_in, const int* in_sizes, int n_in,
                              void* d_out, int out_size) {
    const float* x = (const float*)d_in[0];
    const float* c = (const float*)d_in[1];
    float* out = (float*)d_out;
    const int n = in_sizes[0];   // 8192

    ham_kernel<<<NBLOCKS, TPB>>>(x, c, out, n);
}